// round 6
// baseline (speedup 1.0000x reference)
#include <cuda_runtime.h>
#include <cuda_bf16.h>

#define NATOMS 512
#define NBATCH 16
#define NP 16

// ---- packed f32x2 helpers (FFMA2/FMUL2 paths ptxas won't emit from C++) ----
__device__ __forceinline__ unsigned long long pk2(float lo, float hi) {
    unsigned long long r;
    asm("mov.b64 %0, {%1, %2};" : "=l"(r) : "f"(lo), "f"(hi));
    return r;
}
__device__ __forceinline__ void upk2(float& lo, float& hi, unsigned long long v) {
    asm("mov.b64 {%0, %1}, %2;" : "=f"(lo), "=f"(hi) : "l"(v));
}
__device__ __forceinline__ unsigned long long mul2(unsigned long long a, unsigned long long b) {
    unsigned long long r;
    asm("mul.rn.f32x2 %0, %1, %2;" : "=l"(r) : "l"(a), "l"(b));
    return r;
}
__device__ __forceinline__ unsigned long long fma2(unsigned long long a, unsigned long long b,
                                                   unsigned long long c) {
    unsigned long long r;
    asm("fma.rn.f32x2 %0, %1, %2, %3;" : "=l"(r) : "l"(a), "l"(b), "l"(c));
    return r;
}

__global__ void __launch_bounds__(256) aev_radial_kernel(
    const float* __restrict__ dmat,   // [B, N, N]
    const float* __restrict__ zall,   // [B, N]
    float* __restrict__ out)          // [B, N, 16]
{
    constexpr float RCR       = 5.2f;
    constexpr float PI_OVER_R = 3.14159265358979323846f / 5.2f;
    // log2-domain Gaussian constants: eta=16, shift0=0.9, dshift=0.26875
    constexpr double L2E = 1.4426950408889634;
    constexpr double ETA = 16.0, DSH = 0.26875;
    constexpr float  C2  = (float)(-ETA * L2E);             // -eta*log2e
    constexpr float  A1  = (float)( 2.0 * ETA * DSH * L2E); //  2*eta*dshf*log2e
    constexpr float  A0  = (float)(-ETA * DSH * DSH * L2E); // -eta*dshf^2*log2e
    constexpr double RQd = 0.09913776814937592;             // exp(-2*eta*dshf^2)
    constexpr float  RQ  = (float)RQd;
    constexpr float  RQ3 = (float)(RQd * RQd * RQd);
    constexpr float  RQ4 = (float)(RQd * RQd * RQd * RQd);  // inter-group q ratio
    constexpr float  GSP = 1.075f;                          // 4*dshf

    const int wg   = (blockIdx.x * blockDim.x + threadIdx.x) >> 5;  // b*512 + i
    const int lane = threadIdx.x & 31;
    const int b    = wg >> 9;

    const float* __restrict__ row  = dmat + (size_t)wg * NATOMS;
    const float* __restrict__ zrow = zall + (size_t)b  * NATOMS;

    // packed accumulators: accA[k]={p4k,p4k+1}, accB[k]={p4k+2,p4k+3}
    unsigned long long accA[4], accB[4];
#pragma unroll
    for (int k = 0; k < 4; ++k) { accA[k] = 0ull; accB[k] = 0ull; }

#pragma unroll
    for (int it = 0; it < 4; ++it) {
        const int j0 = it * 128 + lane * 4;
        const float4 dv = *reinterpret_cast<const float4*>(row  + j0);
        const float4 zv = *reinterpret_cast<const float4*>(zrow + j0);
        const float dd[4] = {dv.x, dv.y, dv.z, dv.w};
        const float zz[4] = {zv.x, zv.y, zv.z, zv.w};

#pragma unroll
        for (int e = 0; e < 4; ++e) {
            const float dj = dd[e];
            // cutoff weight; mask (0 < d < RCR) as one range-compare
            float c;
            asm("cos.approx.ftz.f32 %0, %1;" : "=f"(c) : "f"(dj * PI_OVER_R));
            const float fc = fmaf(0.5f, c, 0.5f);
            const float wz = zz[e] * fc;
            const float w  = (fabsf(dj - 2.6f) < 2.6f) ? wz : 0.0f;
            const unsigned long long Wp = pk2(w, w);

            // clamp for the Gaussian path only: prevents q^2 overflow for
            // masked d in (5.2, 10]; w=0 kills the (wrong) clamped values.
            const float dg = fminf(dj, RCR);
            float u = dg - 0.9f;                       // offset from shift 0

            // single ex2 for the step ratio; q_{k+1} = q_k * RQ^4
            float q;
            asm("ex2.approx.ftz.f32 %0, %1;" : "=f"(q) : "f"(fmaf(A1, u, A0)));

#pragma unroll
            for (int k = 0; k < 4; ++k) {
                float g0;
                asm("ex2.approx.ftz.f32 %0, %1;" : "=f"(g0) : "f"((C2 * u) * u));
                const float g1 = g0 * q;
                const unsigned long long G01 = pk2(g0, g1);
                const float s  = q * q;
                const float t1 = s * RQ;               // g2/g0
                const float t2 = s * RQ3;              // g3/g1
                const unsigned long long G23 = mul2(G01, pk2(t1, t2));
                accA[k] = fma2(Wp, G01, accA[k]);
                accB[k] = fma2(Wp, G23, accB[k]);
                if (k < 3) { u -= GSP; q *= RQ4; }
            }
        }
    }

    // unpack accumulators
    float a[NP];
#pragma unroll
    for (int k = 0; k < 4; ++k) {
        upk2(a[4*k + 0], a[4*k + 1], accA[k]);
        upk2(a[4*k + 2], a[4*k + 3], accB[k]);
    }

    // halving reduction: 16 regs -> 1 reg across 32 lanes.
    // After offs {16,8,4,2}, lane holds feature (lane>>1)&15 summed over the
    // 16 lanes sharing its bit0; off=1 completes the 32-lane sum.
    const unsigned FULL = 0xffffffffu;
#pragma unroll
    for (int v = 0; v < 8; ++v) {
        const bool hi = (lane & 16);
        const float send = hi ? a[v] : a[v + 8];
        const float r = __shfl_xor_sync(FULL, send, 16);
        a[v] = (hi ? a[v + 8] : a[v]) + r;
    }
#pragma unroll
    for (int v = 0; v < 4; ++v) {
        const bool hi = (lane & 8);
        const float send = hi ? a[v] : a[v + 4];
        const float r = __shfl_xor_sync(FULL, send, 8);
        a[v] = (hi ? a[v + 4] : a[v]) + r;
    }
#pragma unroll
    for (int v = 0; v < 2; ++v) {
        const bool hi = (lane & 4);
        const float send = hi ? a[v] : a[v + 2];
        const float r = __shfl_xor_sync(FULL, send, 4);
        a[v] = (hi ? a[v + 2] : a[v]) + r;
    }
    {
        const bool hi = (lane & 2);
        const float send = hi ? a[0] : a[1];
        const float r = __shfl_xor_sync(FULL, send, 2);
        a[0] = (hi ? a[1] : a[0]) + r;
    }
    a[0] += __shfl_xor_sync(FULL, a[0], 1);

    if ((lane & 1) == 0) {
        out[(size_t)wg * NP + ((lane >> 1) & 15)] = a[0];
    }
}

extern "C" void kernel_launch(void* const* d_in, const int* in_sizes, int n_in,
                              void* d_out, int out_size)
{
    const float* dmat = (const float*)d_in[0];   // [16, 512, 512] float32
    const float* zall = (const float*)d_in[1];   // [16, 512] float32
    float* out        = (float*)d_out;           // [16, 512, 16] float32

    const int rows = NBATCH * NATOMS;            // 8192 warps
    const int threads = 256;                     // 8 warps / block
    const int blocks = rows / (threads / 32);    // 1024
    aev_radial_kernel<<<blocks, threads>>>(dmat, zall, out);
}

// round 9
// speedup vs baseline: 1.4041x; 1.4041x over previous
#include <cuda_runtime.h>
#include <cuda_bf16.h>

#define NATOMS 512
#define NBATCH 16
#define NP 16

// ---- packed f32x2 helpers ----
__device__ __forceinline__ unsigned long long pk2(float lo, float hi) {
    unsigned long long r;
    asm("mov.b64 %0, {%1, %2};" : "=l"(r) : "f"(lo), "f"(hi));
    return r;
}
__device__ __forceinline__ void upk2(float& lo, float& hi, unsigned long long v) {
    asm("mov.b64 {%0, %1}, %2;" : "=f"(lo), "=f"(hi) : "l"(v));
}
__device__ __forceinline__ unsigned long long mul2(unsigned long long a, unsigned long long b) {
    unsigned long long r;
    asm("mul.rn.f32x2 %0, %1, %2;" : "=l"(r) : "l"(a), "l"(b));
    return r;
}
__device__ __forceinline__ unsigned long long fma2(unsigned long long a, unsigned long long b,
                                                   unsigned long long c) {
    unsigned long long r;
    asm("fma.rn.f32x2 %0, %1, %2, %3;" : "=l"(r) : "l"(a), "l"(b), "l"(c));
    return r;
}

__global__ void __launch_bounds__(128) aev_radial_kernel(
    const float* __restrict__ dmat,   // [B, N, N]
    const float* __restrict__ zall,   // [B, N]
    float* __restrict__ out)          // [B, N, 16]
{
    constexpr float RCR       = 5.2f;
    constexpr float PI_OVER_R = 3.14159265358979323846f / 5.2f;
    // log2-domain Gaussian constants: eta=16, shift0=0.9, dshift=0.26875
    constexpr double L2E = 1.4426950408889634;
    constexpr double ETA = 16.0, DSH = 0.26875;
    constexpr float  C2  = (float)(-ETA * L2E);             // -eta*log2e
    constexpr float  A1  = (float)( 2.0 * ETA * DSH * L2E); //  2*eta*dshf*log2e
    constexpr float  A0  = (float)(-ETA * DSH * DSH * L2E); // -eta*dshf^2*log2e
    constexpr double RQd = 0.09913776814937592;             // exp(-2*eta*dshf^2)
    constexpr float  RQ  = (float)RQd;
    constexpr float  RQ3 = (float)(RQd * RQd * RQd);
    constexpr float  RQ4 = (float)(RQd * RQd * RQd * RQd);  // inter-group q ratio
    constexpr float  RQ8 = (float)(RQd*RQd*RQd*RQd*RQd*RQd*RQd*RQd); // T ratio
    constexpr float  GSP = 1.075f;                          // 4*dshf

    const int warp_g = (blockIdx.x * blockDim.x + threadIdx.x) >> 5;  // 0..4095
    const int lane   = threadIdx.x & 31;
    const int b      = warp_g >> 8;          // batch 0..15
    const int i0     = warp_g & 255;         // base row within batch

    const float* __restrict__ zrow = zall + (size_t)b * NATOMS;
    const unsigned long long RQ8P  = pk2(RQ8, RQ8);
    const unsigned FULL = 0xffffffffu;

    // each warp computes two rows: i0 and i0+256 (same batch -> shared z row)
#pragma unroll 1
    for (int half = 0; half < 2; ++half) {
        const int wg = b * NATOMS + i0 + half * 256;
        const float* __restrict__ row = dmat + (size_t)wg * NATOMS;

        // packed accumulators: accA[k]={p4k,p4k+1}, accB[k]={p4k+2,p4k+3}
        unsigned long long accA[4], accB[4];
#pragma unroll
        for (int k = 0; k < 4; ++k) { accA[k] = 0ull; accB[k] = 0ull; }

#pragma unroll
        for (int it = 0; it < 4; ++it) {
            const int j0 = it * 128 + lane * 4;
            const float4 dv = *reinterpret_cast<const float4*>(row  + j0);
            const float4 zv = *reinterpret_cast<const float4*>(zrow + j0);
            const float dd[4] = {dv.x, dv.y, dv.z, dv.w};
            const float zz[4] = {zv.x, zv.y, zv.z, zv.w};

#pragma unroll
            for (int e = 0; e < 4; ++e) {
                const float dj = dd[e];
                // cutoff weight; mask (0 < d < RCR) as one range-compare
                float c;
                asm("cos.approx.ftz.f32 %0, %1;" : "=f"(c) : "f"(dj * PI_OVER_R));
                const float fc = fmaf(0.5f, c, 0.5f);
                const float wz = zz[e] * fc;
                const float w  = (fabsf(dj - 2.6f) < 2.6f) ? wz : 0.0f;
                const unsigned long long Wp = pk2(w, w);

                // clamp Gaussian path only (masked d>RCR would overflow q^2)
                const float dg = fminf(dj, RCR);
                const float u0 = dg - 0.9f;

                // one ex2 for the step ratio; q_{k+1} = q_k * RQ4
                float q;
                asm("ex2.approx.ftz.f32 %0, %1;" : "=f"(q) : "f"(fmaf(A1, u0, A0)));
                // packed {g2/g0, g3/g1}; T_{k+1} = T_k * RQ8 (packed)
                const float s = q * q;
                unsigned long long T = pk2(s * RQ, s * RQ3);

                // independent group offsets (no serial u chain)
                const float u1 = u0 - GSP;
                const float u2 = u0 - 2.0f * GSP;
                const float u3 = u0 - 3.0f * GSP;

#pragma unroll
                for (int k = 0; k < 4; ++k) {
                    const float uk = (k == 0) ? u0 : (k == 1) ? u1 : (k == 2) ? u2 : u3;
                    float g0;
                    asm("ex2.approx.ftz.f32 %0, %1;"
                        : "=f"(g0) : "f"((C2 * uk) * uk));
                    const float g1 = g0 * q;
                    const unsigned long long G01 = pk2(g0, g1);
                    const unsigned long long G23 = mul2(G01, T);
                    accA[k] = fma2(Wp, G01, accA[k]);
                    accB[k] = fma2(Wp, G23, accB[k]);
                    if (k < 3) { q *= RQ4; T = mul2(T, RQ8P); }
                }
            }
        }

        // unpack
        float a[NP];
#pragma unroll
        for (int k = 0; k < 4; ++k) {
            upk2(a[4*k + 0], a[4*k + 1], accA[k]);
            upk2(a[4*k + 2], a[4*k + 3], accB[k]);
        }

        // halving reduction: 16 regs -> 1 reg across 32 lanes
#pragma unroll
        for (int v = 0; v < 8; ++v) {
            const bool hi = (lane & 16);
            const float send = hi ? a[v] : a[v + 8];
            const float r = __shfl_xor_sync(FULL, send, 16);
            a[v] = (hi ? a[v + 8] : a[v]) + r;
        }
#pragma unroll
        for (int v = 0; v < 4; ++v) {
            const bool hi = (lane & 8);
            const float send = hi ? a[v] : a[v + 4];
            const float r = __shfl_xor_sync(FULL, send, 8);
            a[v] = (hi ? a[v + 4] : a[v]) + r;
        }
#pragma unroll
        for (int v = 0; v < 2; ++v) {
            const bool hi = (lane & 4);
            const float send = hi ? a[v] : a[v + 2];
            const float r = __shfl_xor_sync(FULL, send, 4);
            a[v] = (hi ? a[v + 2] : a[v]) + r;
        }
        {
            const bool hi = (lane & 2);
            const float send = hi ? a[0] : a[1];
            const float r = __shfl_xor_sync(FULL, send, 2);
            a[0] = (hi ? a[1] : a[0]) + r;
        }
        a[0] += __shfl_xor_sync(FULL, a[0], 1);

        if ((lane & 1) == 0) {
            out[(size_t)wg * NP + ((lane >> 1) & 15)] = a[0];
        }
    }
}

extern "C" void kernel_launch(void* const* d_in, const int* in_sizes, int n_in,
                              void* d_out, int out_size)
{
    const float* dmat = (const float*)d_in[0];   // [16, 512, 512] float32
    const float* zall = (const float*)d_in[1];   // [16, 512] float32
    float* out        = (float*)d_out;           // [16, 512, 16] float32

    // 1024 blocks x 128 threads = 4096 warps; each warp does 2 rows.
    // Single balanced wave: ~7 CTAs/SM needed, reg capacity ~10.
    aev_radial_kernel<<<1024, 128>>>(dmat, zall, out);
}